// round 3
// baseline (speedup 1.0000x reference)
#include <cuda_runtime.h>
#include <math.h>
#include <string.h>

// Problem constants
#define NN   1024
#define MUL  128
#define CH   128
#define RBq  20
#define RAq  19
#define DX   9     // (L1+1)^2 = (L2+1)^2
#define DZ   25    // (LZ+1)^2
#define MAXG 480

#define SCALE_IN  0.08838834764831845f   // 1/sqrt(128)
#define SCALE_OUT 0.08838834764831845f   // 1/sqrt(128)

// Sparse Gaunt table, passed by value as kernel parameter (constant memory).
struct GTab {
    int   start[DZ + 1];   // CSR segments per output d
    int   idx[MAXG];       // (d1 << 8) | d2
    float coef[MAXG];
};

// Intermediate z in transposed layout [n][d][c] (c contiguous = GEMM K-dim)
__device__ float g_zt[NN * DZ * CH];

// ---------------------------------------------------------------------------
// Host: build the Gaunt table (double precision, exact same quadrature as ref)
// ---------------------------------------------------------------------------
static double assoc_legendre_h(int l, int m, double x) {
    double pmm = 1.0;
    if (m > 0) {
        double df = 1.0;
        for (int i = 1; i < 2 * m; i += 2) df *= (double)i;
        pmm = ((m & 1) ? -1.0 : 1.0) * df * pow(1.0 - x * x, 0.5 * m);
    }
    if (l == m) return pmm;
    double pmmp1 = x * (2 * m + 1) * pmm;
    if (l == m + 1) return pmmp1;
    double p = pmmp1;
    for (int ll = m + 2; ll <= l; ++ll) {
        p = ((2 * ll - 1) * x * pmmp1 - (ll + m - 1) * pmm) / (ll - m);
        pmm = pmmp1; pmmp1 = p;
    }
    return pmmp1;
}

static void build_gtab(GTab* gt) {
    double ct[RBq], qw[RBq];
    const int n = RBq;
    for (int i = 0; i < n; ++i) {
        double z = cos(M_PI * (i + 0.75) / (n + 0.5));
        double pp = 1.0;
        for (int it = 0; it < 100; ++it) {
            double p1 = 1.0, p2 = 0.0;
            for (int j = 1; j <= n; ++j) {
                double p3 = p2; p2 = p1;
                p1 = ((2.0 * j - 1.0) * z * p2 - (j - 1.0) * p3) / (double)j;
            }
            pp = n * (z * p1 - p2) / (z * z - 1.0);
            double dz = p1 / pp;
            z -= dz;
            if (fabs(dz) < 1e-15) break;
        }
        ct[i] = z;
        qw[i] = 2.0 / ((1.0 - z * z) * pp * pp);
    }

    static double Y[DZ][RBq][RAq];
    for (int l = 0; l <= 4; ++l) {
        for (int m = -l; m <= l; ++m) {
            int am = m < 0 ? -m : m;
            double f1 = 1.0, f2 = 1.0;
            for (int i = 2; i <= l - am; ++i) f1 *= (double)i;
            for (int i = 2; i <= l + am; ++i) f2 *= (double)i;
            double nlm = sqrt((2.0 * l + 1.0) / (4.0 * M_PI) * f1 / f2);
            for (int b = 0; b < RBq; ++b) {
                double P = assoc_legendre_h(l, am, ct[b]);
                for (int a = 0; a < RAq; ++a) {
                    double alpha = 2.0 * M_PI * (double)a / (double)RAq;
                    double ang;
                    if (m == 0)      ang = 1.0;
                    else if (m > 0)  ang = sqrt(2.0) * cos(m * alpha);
                    else             ang = sqrt(2.0) * sin(am * alpha);
                    Y[l * l + l + m][b][a] = nlm * P * ang;
                }
            }
        }
    }

    int cnt = 0;
    for (int d = 0; d < DZ; ++d) {
        gt->start[d] = cnt;
        for (int d1 = 0; d1 < DX; ++d1) {
            for (int d2 = 0; d2 < DX; ++d2) {
                double s = 0.0;
                for (int b = 0; b < RBq; ++b) {
                    double rs = 0.0;
                    for (int a = 0; a < RAq; ++a)
                        rs += Y[d][b][a] * Y[d1][b][a] * Y[d2][b][a];
                    s += rs * qw[b];
                }
                s *= 2.0 * M_PI / (double)RAq;
                if (fabs(s) > 1e-8 && cnt < MAXG) {
                    gt->idx[cnt]  = (d1 << 8) | d2;
                    gt->coef[cnt] = (float)s;
                    ++cnt;
                }
            }
        }
    }
    gt->start[DZ] = cnt;
    for (int k = cnt; k < MAXG; ++k) { gt->idx[k] = 0; gt->coef[k] = 0.0f; }
}

// ---------------------------------------------------------------------------
// Kernel 1 (fused): per-l linear_in for x and y + sparse Gaunt contraction.
// 4 nodes / CTA, 128 threads (thread = channel c). Writes z_t[n][d][c].
// Dynamic smem: xs (4*128*12) | xcs (4*128*9) | ycs (4*128*9) = 61440 B
// ---------------------------------------------------------------------------
__global__ void __launch_bounds__(128) k_front(
    const float* __restrict__ x, const float* __restrict__ y,
    const float* __restrict__ wx, const float* __restrict__ wy, GTab gt)
{
    extern __shared__ float sm_f[];
    float* xs  = sm_f;                  // input staging (padded 9->12)
    float* xcs = xs  + 4 * MUL * 12;    // xc rows [j*128+c][9]
    float* ycs = xcs + 4 * MUL * DX;    // yc rows

    const int c  = threadIdx.x;
    const int n0 = blockIdx.x * 4;

    for (int pass = 0; pass < 2; ++pass) {
        const float* src = pass ? y   : x;
        const float* w   = pass ? wy  : wx;
        float*       dst = pass ? ycs : xcs;

        __syncthreads();   // all reads of xs from previous pass are done
        for (int i = c; i < 4 * MUL * DX; i += 128) {
            int j = i / (MUL * DX);
            int r = i - j * (MUL * DX);
            int m = r / DX;
            int d = r - m * DX;
            xs[(j * MUL + m) * 12 + d] = src[(size_t)(n0 + j) * (MUL * DX) + r];
        }
        __syncthreads();

        float acc[4][9];
        #pragma unroll
        for (int j = 0; j < 4; ++j)
            #pragma unroll
            for (int d = 0; d < 9; ++d) acc[j][d] = 0.0f;

        const float* wc = w + c;
        for (int m = 0; m < MUL; ++m) {
            float w0 = wc[(0 * MUL + m) * CH];
            float w1 = wc[(1 * MUL + m) * CH];
            float w2 = wc[(2 * MUL + m) * CH];
            #pragma unroll
            for (int j = 0; j < 4; ++j) {
                const float4* p = (const float4*)&xs[(j * MUL + m) * 12];
                float4 a = p[0];
                float4 b = p[1];
                float  e = xs[(j * MUL + m) * 12 + 8];
                acc[j][0] = fmaf(w0, a.x, acc[j][0]);
                acc[j][1] = fmaf(w1, a.y, acc[j][1]);
                acc[j][2] = fmaf(w1, a.z, acc[j][2]);
                acc[j][3] = fmaf(w1, a.w, acc[j][3]);
                acc[j][4] = fmaf(w2, b.x, acc[j][4]);
                acc[j][5] = fmaf(w2, b.y, acc[j][5]);
                acc[j][6] = fmaf(w2, b.z, acc[j][6]);
                acc[j][7] = fmaf(w2, b.w, acc[j][7]);
                acc[j][8] = fmaf(w2, e,   acc[j][8]);
            }
        }

        // thread-private rows: no sync needed (only this thread reads them)
        #pragma unroll
        for (int j = 0; j < 4; ++j)
            #pragma unroll
            for (int d = 0; d < 9; ++d)
                dst[(j * CH + c) * DX + d] = acc[j][d] * SCALE_IN;
    }

    // ---- sparse Gaunt: thread c reads only its own rows, writes z_t ----
    #pragma unroll
    for (int j = 0; j < 4; ++j) {
        const float* xr = &xcs[(j * CH + c) * DX];
        const float* yr = &ycs[(j * CH + c) * DX];
        float* ob = &g_zt[((size_t)(n0 + j) * DZ) * CH + c];
        for (int d = 0; d < DZ; ++d) {
            float z = 0.0f;
            const int e0 = gt.start[d], e1 = gt.start[d + 1];
            for (int k = e0; k < e1; ++k) {
                const int id = gt.idx[k];
                z = fmaf(gt.coef[k], xr[id >> 8] * yr[id & 255], z);
            }
            ob[d * CH] = z * SCALE_OUT;   // coalesced across c
        }
    }
}

// ---------------------------------------------------------------------------
// Kernel 2: per-l linear_out as a blocked SGEMM.
//   out[n,e,d(l)] = sum_c z_t[n,d,c] * wz[l,c,e]
// grid = (row_tile, l); CTA: 64 rows x 128 e, K = 128. 256 threads,
// 4x8 register micro-tiles. Dynamic smem: As 64x132 + Bs 128x128 = 99328 B
// ---------------------------------------------------------------------------
__global__ void __launch_bounds__(256) k_out(
    const float* __restrict__ wz, float* __restrict__ out)
{
    extern __shared__ float sm[];
    float* As = sm;              // [64][132] (pad 4)
    float* Bs = sm + 64 * 132;   // [128][128] : Bs[c][e] = wz[l][c][e]

    const int l   = blockIdx.y;
    const int dl  = 2 * l + 1;
    const int Rl  = NN * dl;
    const int t0  = blockIdx.x * 64;
    if (t0 >= Rl) return;
    const int tid = threadIdx.x;

    // Load wz[l] into Bs (float4, coalesced)
    {
        const float4* w4 = (const float4*)(wz + (size_t)l * CH * CH);
        float4* b4 = (float4*)Bs;
        #pragma unroll
        for (int i = 0; i < 16; ++i)
            b4[tid + i * 256] = w4[tid + i * 256];
    }
    // Load A tile: 64 rows (global row r = t0+m -> (n, d)) x 128 k, coalesced
    #pragma unroll
    for (int q = 0; q < 8; ++q) {
        int fi = q * 256 + tid;          // 0..2047 float4 slots
        int m  = fi >> 5;                // row in tile
        int kq = fi & 31;                // float4 index along k
        int r  = t0 + m;
        int n  = r / dl;
        int dg = l * l + (r - n * dl);
        float4 v = *(const float4*)&g_zt[((size_t)n * DZ + dg) * CH + kq * 4];
        *(float4*)&As[m * 132 + kq * 4] = v;
    }
    __syncthreads();

    const int m0 = (tid >> 4) * 4;
    const int e0 = (tid & 15) * 8;

    float acc[4][8];
    #pragma unroll
    for (int i = 0; i < 4; ++i)
        #pragma unroll
        for (int j = 0; j < 8; ++j) acc[i][j] = 0.0f;

    #pragma unroll 8
    for (int k = 0; k < 128; ++k) {
        float a0 = As[(m0 + 0) * 132 + k];
        float a1 = As[(m0 + 1) * 132 + k];
        float a2 = As[(m0 + 2) * 132 + k];
        float a3 = As[(m0 + 3) * 132 + k];
        float4 b0 = *(const float4*)&Bs[k * CH + e0];
        float4 b1 = *(const float4*)&Bs[k * CH + e0 + 4];
        float bv[8] = {b0.x, b0.y, b0.z, b0.w, b1.x, b1.y, b1.z, b1.w};
        #pragma unroll
        for (int j = 0; j < 8; ++j) {
            acc[0][j] = fmaf(a0, bv[j], acc[0][j]);
            acc[1][j] = fmaf(a1, bv[j], acc[1][j]);
            acc[2][j] = fmaf(a2, bv[j], acc[2][j]);
            acc[3][j] = fmaf(a3, bv[j], acc[3][j]);
        }
    }

    // Store: out[n*3200 + e*25 + d]
    #pragma unroll
    for (int i = 0; i < 4; ++i) {
        int r  = t0 + m0 + i;
        int n  = r / dl;
        int dg = l * l + (r - n * dl);
        float* op = out + (size_t)n * (CH * DZ) + dg;
        #pragma unroll
        for (int j = 0; j < 8; ++j)
            op[(size_t)(e0 + j) * DZ] = acc[i][j];
    }
}

// ---------------------------------------------------------------------------
extern "C" void kernel_launch(void* const* d_in, const int* in_sizes, int n_in,
                              void* d_out, int out_size)
{
    const float* x  = (const float*)d_in[0];
    const float* y  = (const float*)d_in[1];
    const float* wx = (const float*)d_in[2];
    const float* wy = (const float*)d_in[3];
    const float* wz = (const float*)d_in[4];
    float* out = (float*)d_out;

    GTab gt;
    build_gtab(&gt);

    const int smem_front = (4 * MUL * 12 + 2 * 4 * MUL * DX) * 4;   // 61440
    const int smem_out   = (64 * 132 + CH * CH) * 4;                // 99328
    cudaFuncSetAttribute(k_front, cudaFuncAttributeMaxDynamicSharedMemorySize, smem_front);
    cudaFuncSetAttribute(k_out,   cudaFuncAttributeMaxDynamicSharedMemorySize, smem_out);

    k_front<<<NN / 4, 128, smem_front>>>(x, y, wx, wy, gt);

    dim3 g2(144, 5);   // 144 = 9216/64 rows for l=4; smaller l exit early
    k_out<<<g2, 256, smem_out>>>(wz, out);
}

// round 5
// speedup vs baseline: 1.2072x; 1.2072x over previous
#include <cuda_runtime.h>
#include <math.h>
#include <string.h>

// Problem constants
#define NN   1024
#define MUL  128
#define CH   128
#define RBq  20
#define RAq  19
#define DX   9     // (L1+1)^2 = (L2+1)^2
#define DZ   25    // (LZ+1)^2
#define MAXG 480

#define SCALE_IN  0.08838834764831845f   // 1/sqrt(128)
#define SCALE_OUT 0.08838834764831845f   // 1/sqrt(128)

// Sparse Gaunt table, passed by value as kernel parameter (constant memory).
struct GTab {
    int   start[DZ + 1];
    int   idx[MAXG];       // (d1 << 8) | d2
    float coef[MAXG];
};

// Intermediates, all transposed [n][d][c] (c contiguous)
__device__ float g_xct[NN * DX * CH];
__device__ float g_yct[NN * DX * CH];
__device__ float g_zt [NN * DZ * CH];

// ---------------------------------------------------------------------------
// Host: build the Gaunt table (double precision, exact quadrature as ref)
// ---------------------------------------------------------------------------
static double assoc_legendre_h(int l, int m, double x) {
    double pmm = 1.0;
    if (m > 0) {
        double df = 1.0;
        for (int i = 1; i < 2 * m; i += 2) df *= (double)i;
        pmm = ((m & 1) ? -1.0 : 1.0) * df * pow(1.0 - x * x, 0.5 * m);
    }
    if (l == m) return pmm;
    double pmmp1 = x * (2 * m + 1) * pmm;
    if (l == m + 1) return pmmp1;
    double p = pmmp1;
    for (int ll = m + 2; ll <= l; ++ll) {
        p = ((2 * ll - 1) * x * pmmp1 - (ll + m - 1) * pmm) / (ll - m);
        pmm = pmmp1; pmmp1 = p;
    }
    return pmmp1;
}

static void build_gtab(GTab* gt) {
    double ct[RBq], qw[RBq];
    const int n = RBq;
    for (int i = 0; i < n; ++i) {
        double z = cos(M_PI * (i + 0.75) / (n + 0.5));
        double pp = 1.0;
        for (int it = 0; it < 100; ++it) {
            double p1 = 1.0, p2 = 0.0;
            for (int j = 1; j <= n; ++j) {
                double p3 = p2; p2 = p1;
                p1 = ((2.0 * j - 1.0) * z * p2 - (j - 1.0) * p3) / (double)j;
            }
            pp = n * (z * p1 - p2) / (z * z - 1.0);
            double dz = p1 / pp;
            z -= dz;
            if (fabs(dz) < 1e-15) break;
        }
        ct[i] = z;
        qw[i] = 2.0 / ((1.0 - z * z) * pp * pp);
    }

    static double Y[DZ][RBq][RAq];
    for (int l = 0; l <= 4; ++l) {
        for (int m = -l; m <= l; ++m) {
            int am = m < 0 ? -m : m;
            double f1 = 1.0, f2 = 1.0;
            for (int i = 2; i <= l - am; ++i) f1 *= (double)i;
            for (int i = 2; i <= l + am; ++i) f2 *= (double)i;
            double nlm = sqrt((2.0 * l + 1.0) / (4.0 * M_PI) * f1 / f2);
            for (int b = 0; b < RBq; ++b) {
                double P = assoc_legendre_h(l, am, ct[b]);
                for (int a = 0; a < RAq; ++a) {
                    double alpha = 2.0 * M_PI * (double)a / (double)RAq;
                    double ang;
                    if (m == 0)      ang = 1.0;
                    else if (m > 0)  ang = sqrt(2.0) * cos(m * alpha);
                    else             ang = sqrt(2.0) * sin(am * alpha);
                    Y[l * l + l + m][b][a] = nlm * P * ang;
                }
            }
        }
    }

    int cnt = 0;
    for (int d = 0; d < DZ; ++d) {
        gt->start[d] = cnt;
        for (int d1 = 0; d1 < DX; ++d1) {
            for (int d2 = 0; d2 < DX; ++d2) {
                double s = 0.0;
                for (int b = 0; b < RBq; ++b) {
                    double rs = 0.0;
                    for (int a = 0; a < RAq; ++a)
                        rs += Y[d][b][a] * Y[d1][b][a] * Y[d2][b][a];
                    s += rs * qw[b];
                }
                s *= 2.0 * M_PI / (double)RAq;
                if (fabs(s) > 1e-8 && cnt < MAXG) {
                    gt->idx[cnt]  = (d1 << 8) | d2;
                    gt->coef[cnt] = (float)s;
                    ++cnt;
                }
            }
        }
    }
    gt->start[DZ] = cnt;
    for (int k = cnt; k < MAXG; ++k) { gt->idx[k] = 0; gt->coef[k] = 0.0f; }
}

// ---------------------------------------------------------------------------
// Kernel 1: per-l linear_in for x and y (round-1 proven config, 24KB smem).
// 4 nodes / CTA, 128 threads (thread = channel c). Output transposed [n][d][c].
// ---------------------------------------------------------------------------
__global__ void __launch_bounds__(128) k_lin_in(
    const float* __restrict__ x, const float* __restrict__ y,
    const float* __restrict__ wx, const float* __restrict__ wy)
{
    __shared__ float xs[4 * MUL * 12];   // pad 9 -> 12 for float4 loads (24 KB)
    const int c  = threadIdx.x;
    const int n0 = blockIdx.x * 4;

    for (int pass = 0; pass < 2; ++pass) {
        const float* src = pass ? y     : x;
        const float* w   = pass ? wy    : wx;
        float*       dst = pass ? g_yct : g_xct;

        __syncthreads();
        for (int i = c; i < 4 * MUL * DX; i += 128) {
            int j = i / (MUL * DX);
            int r = i - j * (MUL * DX);
            int m = r / DX;
            int d = r - m * DX;
            xs[(j * MUL + m) * 12 + d] = src[(size_t)(n0 + j) * (MUL * DX) + r];
        }
        __syncthreads();

        float acc[4][9];
        #pragma unroll
        for (int j = 0; j < 4; ++j)
            #pragma unroll
            for (int d = 0; d < 9; ++d) acc[j][d] = 0.0f;

        const float* wc = w + c;
        for (int m = 0; m < MUL; ++m) {
            float w0 = wc[(0 * MUL + m) * CH];
            float w1 = wc[(1 * MUL + m) * CH];
            float w2 = wc[(2 * MUL + m) * CH];
            #pragma unroll
            for (int j = 0; j < 4; ++j) {
                const float4* p = (const float4*)&xs[(j * MUL + m) * 12];
                float4 a = p[0];
                float4 b = p[1];
                float  e = xs[(j * MUL + m) * 12 + 8];
                acc[j][0] = fmaf(w0, a.x, acc[j][0]);
                acc[j][1] = fmaf(w1, a.y, acc[j][1]);
                acc[j][2] = fmaf(w1, a.z, acc[j][2]);
                acc[j][3] = fmaf(w1, a.w, acc[j][3]);
                acc[j][4] = fmaf(w2, b.x, acc[j][4]);
                acc[j][5] = fmaf(w2, b.y, acc[j][5]);
                acc[j][6] = fmaf(w2, b.z, acc[j][6]);
                acc[j][7] = fmaf(w2, b.w, acc[j][7]);
                acc[j][8] = fmaf(w2, e,   acc[j][8]);
            }
        }

        __syncthreads();
        // stage transposed: [j][d][c]
        #pragma unroll
        for (int j = 0; j < 4; ++j)
            #pragma unroll
            for (int d = 0; d < 9; ++d)
                xs[(j * DX + d) * CH + c] = acc[j][d] * SCALE_IN;
        __syncthreads();
        for (int i = c; i < 4 * DX * CH; i += 128)
            dst[(size_t)n0 * (DX * CH) + i] = xs[i];
    }
}

// ---------------------------------------------------------------------------
// Kernel 2: sparse Gaunt contraction only. 2 nodes/CTA, 128 threads.
// Reads xct/yct [n][d][c], writes zt [n][d][c] (SCALE_OUT folded).
// ---------------------------------------------------------------------------
__global__ void __launch_bounds__(128) k_gaunt(GTab gt)
{
    __shared__ float xcs[2 * DX * CH];
    __shared__ float ycs[2 * DX * CH];

    const int t  = threadIdx.x;
    const int n0 = blockIdx.x * 2;

    for (int i = t; i < 2 * DX * CH; i += 128) {
        xcs[i] = g_xct[(size_t)n0 * DX * CH + i];
        ycs[i] = g_yct[(size_t)n0 * DX * CH + i];
    }
    __syncthreads();

    const float* x0 = xcs + t;
    const float* x1 = xcs + DX * CH + t;
    const float* y0 = ycs + t;
    const float* y1 = ycs + DX * CH + t;
    float* o0 = g_zt + (size_t)n0 * DZ * CH + t;
    float* o1 = o0 + DZ * CH;

    for (int d = 0; d < DZ; ++d) {
        float z0 = 0.0f, z1 = 0.0f;
        const int e0 = gt.start[d], e1 = gt.start[d + 1];
        for (int k = e0; k < e1; ++k) {
            const int   id = gt.idx[k];
            const float cf = gt.coef[k];
            const int a1 = (id >> 8) * CH;
            const int a2 = (id & 255) * CH;
            z0 = fmaf(cf, x0[a1] * y0[a2], z0);
            z1 = fmaf(cf, x1[a1] * y1[a2], z1);
        }
        o0[d * CH] = z0 * SCALE_OUT;
        o1[d * CH] = z1 * SCALE_OUT;
    }
}

// ---------------------------------------------------------------------------
// Kernel 3: linear_out as d-batched double-buffered SGEMM.
//   For fixed d: C[n][e] = sum_c zt[n][d][c] * wz[l(d)][c][e]
// grid (16, 25): CTA = 64 n-rows x 128 e-cols, K = 128 in chunks of 32.
// 256 threads, 4x8 micro-tile. Dynamic smem = 51200 B.
// ---------------------------------------------------------------------------
#define KC  32
#define PAK 36    // A row pitch (32 + 4): conflict-free, float4-aligned

__global__ void __launch_bounds__(256) k_out(
    const float* __restrict__ wz, float* __restrict__ out)
{
    extern __shared__ float sm[];
    float* As = sm;                    // [2][64][PAK]  (row-major, k minor)
    float* Bs = sm + 2 * 64 * PAK;     // [2][KC][128]

    const int d   = blockIdx.y;
    const int l   = (d >= 16) ? 4 : (d >= 9) ? 3 : (d >= 4) ? 2 : (d >= 1) ? 1 : 0;
    const int n0  = blockIdx.x * 64;
    const int tid = threadIdx.x;

    const float* Ab = g_zt + (size_t)n0 * (DZ * CH) + (size_t)d * CH;
    const float* Bb = wz + (size_t)l * (CH * CH);

    // loader lanes
    const int ar  = tid >> 3;     // 0..31 : A row (+32 on 2nd sweep)
    const int as  = tid & 7;      // float4 slot within 32-float k-chunk
    const int be4 = tid & 31;     // B float4 col
    const int bk  = tid >> 5;     // 0..7  : B k row (+8 per sweep)

    float4 pa[2], pb[4];

    // micro-tile lanes
    const int tm = tid >> 4;      // 0..15 -> rows tm*4 .. tm*4+3
    const int te = tid & 15;      // cols te*4..+3 and 64+te*4..+3

    float acc[4][8];
    #pragma unroll
    for (int i = 0; i < 4; ++i)
        #pragma unroll
        for (int j = 0; j < 8; ++j) acc[i][j] = 0.0f;

    // prologue: load chunk 0
    #pragma unroll
    for (int s = 0; s < 2; ++s)
        pa[s] = *(const float4*)(Ab + (size_t)(ar + s * 32) * (DZ * CH) + as * 4);
    #pragma unroll
    for (int s = 0; s < 4; ++s)
        pb[s] = *(const float4*)(Bb + (size_t)(bk + s * 8) * CH + be4 * 4);
    {
        float* A = As; float* B = Bs;
        #pragma unroll
        for (int s = 0; s < 2; ++s)
            *(float4*)(A + (ar + s * 32) * PAK + as * 4) = pa[s];
        #pragma unroll
        for (int s = 0; s < 4; ++s)
            *(float4*)(B + (bk + s * 8) * 128 + be4 * 4) = pb[s];
    }
    __syncthreads();

    for (int kb = 0; kb < 4; ++kb) {
        if (kb < 3) {
            const int ko = (kb + 1) * KC;
            #pragma unroll
            for (int s = 0; s < 2; ++s)
                pa[s] = *(const float4*)(Ab + (size_t)(ar + s * 32) * (DZ * CH) + ko + as * 4);
            #pragma unroll
            for (int s = 0; s < 4; ++s)
                pb[s] = *(const float4*)(Bb + (size_t)(ko + bk + s * 8) * CH + be4 * 4);
        }

        const float* A = As + (kb & 1) * 64 * PAK;
        const float* B = Bs + (kb & 1) * KC * 128;

        #pragma unroll 8
        for (int kk = 0; kk < KC; ++kk) {
            float a0 = A[(tm * 4 + 0) * PAK + kk];
            float a1 = A[(tm * 4 + 1) * PAK + kk];
            float a2 = A[(tm * 4 + 2) * PAK + kk];
            float a3 = A[(tm * 4 + 3) * PAK + kk];
            float4 b0 = *(const float4*)(B + kk * 128 + te * 4);
            float4 b1 = *(const float4*)(B + kk * 128 + 64 + te * 4);
            float bv[8] = {b0.x, b0.y, b0.z, b0.w, b1.x, b1.y, b1.z, b1.w};
            #pragma unroll
            for (int j = 0; j < 8; ++j) {
                acc[0][j] = fmaf(a0, bv[j], acc[0][j]);
                acc[1][j] = fmaf(a1, bv[j], acc[1][j]);
                acc[2][j] = fmaf(a2, bv[j], acc[2][j]);
                acc[3][j] = fmaf(a3, bv[j], acc[3][j]);
            }
        }

        if (kb < 3) {
            __syncthreads();
            float* An = As + ((kb + 1) & 1) * 64 * PAK;
            float* Bn = Bs + ((kb + 1) & 1) * KC * 128;
            #pragma unroll
            for (int s = 0; s < 2; ++s)
                *(float4*)(An + (ar + s * 32) * PAK + as * 4) = pa[s];
            #pragma unroll
            for (int s = 0; s < 4; ++s)
                *(float4*)(Bn + (bk + s * 8) * 128 + be4 * 4) = pb[s];
            __syncthreads();
        }
    }

    // store: out[n][e][d]
    #pragma unroll
    for (int i = 0; i < 4; ++i) {
        const int n = n0 + tm * 4 + i;
        float* op = out + (size_t)n * (CH * DZ) + d;
        #pragma unroll
        for (int j = 0; j < 8; ++j) {
            const int e = (j < 4) ? (te * 4 + j) : (64 + te * 4 + (j - 4));
            op[(size_t)e * DZ] = acc[i][j];
        }
    }
}

// ---------------------------------------------------------------------------
extern "C" void kernel_launch(void* const* d_in, const int* in_sizes, int n_in,
                              void* d_out, int out_size)
{
    const float* x  = (const float*)d_in[0];
    const float* y  = (const float*)d_in[1];
    const float* wx = (const float*)d_in[2];
    const float* wy = (const float*)d_in[3];
    const float* wz = (const float*)d_in[4];
    float* out = (float*)d_out;

    GTab gt;
    build_gtab(&gt);

    const int smem_out = (2 * 64 * PAK + 2 * KC * 128) * 4;   // 51200 B
    cudaFuncSetAttribute(k_out, cudaFuncAttributeMaxDynamicSharedMemorySize, smem_out);

    k_lin_in<<<NN / 4, 128>>>(x, y, wx, wy);
    k_gaunt<<<NN / 2, 128>>>(gt);

    dim3 g3(16, 25);
    k_out<<<g3, 256, smem_out>>>(wz, out);
}

// round 6
// speedup vs baseline: 1.3297x; 1.1015x over previous
#include <cuda_runtime.h>
#include <math.h>
#include <string.h>

// Problem constants
#define NN   1024
#define MUL  128
#define CH   128
#define RBq  20
#define RAq  19
#define DX   9     // (L1+1)^2 = (L2+1)^2
#define DZ   25    // (LZ+1)^2
#define MAXG 480

#define SCALE_IN  0.08838834764831845f   // 1/sqrt(128)
#define SCALE_OUT 0.08838834764831845f   // 1/sqrt(128)

// Sparse Gaunt table, passed by value as kernel parameter (constant memory).
struct GTab {
    int   start[DZ + 1];
    int   idx[MAXG];       // (d1 << 8) | d2
    float coef[MAXG];
};

// Intermediates, all transposed [n][d][c] (c contiguous)
__device__ float g_xct[NN * DX * CH];
__device__ float g_yct[NN * DX * CH];
__device__ float g_zt [NN * DZ * CH];

// ---------------------------------------------------------------------------
// Host: build the Gaunt table (double precision, exact quadrature as ref)
// ---------------------------------------------------------------------------
static double assoc_legendre_h(int l, int m, double x) {
    double pmm = 1.0;
    if (m > 0) {
        double df = 1.0;
        for (int i = 1; i < 2 * m; i += 2) df *= (double)i;
        pmm = ((m & 1) ? -1.0 : 1.0) * df * pow(1.0 - x * x, 0.5 * m);
    }
    if (l == m) return pmm;
    double pmmp1 = x * (2 * m + 1) * pmm;
    if (l == m + 1) return pmmp1;
    double p = pmmp1;
    for (int ll = m + 2; ll <= l; ++ll) {
        p = ((2 * ll - 1) * x * pmmp1 - (ll + m - 1) * pmm) / (ll - m);
        pmm = pmmp1; pmmp1 = p;
    }
    return pmmp1;
}

static void build_gtab(GTab* gt) {
    double ct[RBq], qw[RBq];
    const int n = RBq;
    for (int i = 0; i < n; ++i) {
        double z = cos(M_PI * (i + 0.75) / (n + 0.5));
        double pp = 1.0;
        for (int it = 0; it < 100; ++it) {
            double p1 = 1.0, p2 = 0.0;
            for (int j = 1; j <= n; ++j) {
                double p3 = p2; p2 = p1;
                p1 = ((2.0 * j - 1.0) * z * p2 - (j - 1.0) * p3) / (double)j;
            }
            pp = n * (z * p1 - p2) / (z * z - 1.0);
            double dz = p1 / pp;
            z -= dz;
            if (fabs(dz) < 1e-15) break;
        }
        ct[i] = z;
        qw[i] = 2.0 / ((1.0 - z * z) * pp * pp);
    }

    static double Y[DZ][RBq][RAq];
    for (int l = 0; l <= 4; ++l) {
        for (int m = -l; m <= l; ++m) {
            int am = m < 0 ? -m : m;
            double f1 = 1.0, f2 = 1.0;
            for (int i = 2; i <= l - am; ++i) f1 *= (double)i;
            for (int i = 2; i <= l + am; ++i) f2 *= (double)i;
            double nlm = sqrt((2.0 * l + 1.0) / (4.0 * M_PI) * f1 / f2);
            for (int b = 0; b < RBq; ++b) {
                double P = assoc_legendre_h(l, am, ct[b]);
                for (int a = 0; a < RAq; ++a) {
                    double alpha = 2.0 * M_PI * (double)a / (double)RAq;
                    double ang;
                    if (m == 0)      ang = 1.0;
                    else if (m > 0)  ang = sqrt(2.0) * cos(m * alpha);
                    else             ang = sqrt(2.0) * sin(am * alpha);
                    Y[l * l + l + m][b][a] = nlm * P * ang;
                }
            }
        }
    }

    int cnt = 0;
    for (int d = 0; d < DZ; ++d) {
        gt->start[d] = cnt;
        for (int d1 = 0; d1 < DX; ++d1) {
            for (int d2 = 0; d2 < DX; ++d2) {
                double s = 0.0;
                for (int b = 0; b < RBq; ++b) {
                    double rs = 0.0;
                    for (int a = 0; a < RAq; ++a)
                        rs += Y[d][b][a] * Y[d1][b][a] * Y[d2][b][a];
                    s += rs * qw[b];
                }
                s *= 2.0 * M_PI / (double)RAq;
                if (fabs(s) > 1e-8 && cnt < MAXG) {
                    gt->idx[cnt]  = (d1 << 8) | d2;
                    gt->coef[cnt] = (float)s;
                    ++cnt;
                }
            }
        }
    }
    gt->start[DZ] = cnt;
    for (int k = cnt; k < MAXG; ++k) { gt->idx[k] = 0; gt->coef[k] = 0.0f; }
}

// ---------------------------------------------------------------------------
// Kernel 1: per-l linear_in for x and y, m-split for latency hiding.
// 4 nodes/CTA, 256 threads = 2 m-groups x 128 channels.
// Each group sums m in [g*64, g*64+64); partials reduced via smem.
// Output transposed [n][d][c]. Dynamic smem = 61440 B.
// ---------------------------------------------------------------------------
__global__ void __launch_bounds__(256) k_lin_in(
    const float* __restrict__ x, const float* __restrict__ y,
    const float* __restrict__ wx, const float* __restrict__ wy)
{
    extern __shared__ float sm[];
    float* xs  = sm;                    // 4*128*12 = 6144 floats (pad 9->12)
    float* buf = sm + 4 * MUL * 12;     // 2 slabs * 4608 floats (partials)

    const int tid = threadIdx.x;
    const int c   = tid & 127;
    const int g   = tid >> 7;           // 0 or 1
    const int n0  = blockIdx.x * 4;

    for (int pass = 0; pass < 2; ++pass) {
        const float* src = pass ? y     : x;
        const float* w   = pass ? wy    : wx;
        float*       dst = pass ? g_yct : g_xct;

        __syncthreads();   // previous pass's xs/buf readers are done
        for (int i = tid; i < 4 * MUL * DX; i += 256) {
            int j = i / (MUL * DX);
            int r = i - j * (MUL * DX);
            int m = r / DX;
            int d = r - m * DX;
            xs[(j * MUL + m) * 12 + d] = src[(size_t)(n0 + j) * (MUL * DX) + r];
        }
        __syncthreads();

        float acc[4][9];
        #pragma unroll
        for (int j = 0; j < 4; ++j)
            #pragma unroll
            for (int d = 0; d < 9; ++d) acc[j][d] = 0.0f;

        const float* wc = w + c;
        const int m0 = g * 64;
        for (int mi = 0; mi < 64; ++mi) {
            const int m = m0 + mi;
            float w0 = wc[(0 * MUL + m) * CH];
            float w1 = wc[(1 * MUL + m) * CH];
            float w2 = wc[(2 * MUL + m) * CH];
            #pragma unroll
            for (int j = 0; j < 4; ++j) {
                const float4* p = (const float4*)&xs[(j * MUL + m) * 12];
                float4 a = p[0];
                float4 b = p[1];
                float  e = xs[(j * MUL + m) * 12 + 8];
                acc[j][0] = fmaf(w0, a.x, acc[j][0]);
                acc[j][1] = fmaf(w1, a.y, acc[j][1]);
                acc[j][2] = fmaf(w1, a.z, acc[j][2]);
                acc[j][3] = fmaf(w1, a.w, acc[j][3]);
                acc[j][4] = fmaf(w2, b.x, acc[j][4]);
                acc[j][5] = fmaf(w2, b.y, acc[j][5]);
                acc[j][6] = fmaf(w2, b.z, acc[j][6]);
                acc[j][7] = fmaf(w2, b.w, acc[j][7]);
                acc[j][8] = fmaf(w2, e,   acc[j][8]);
            }
        }

        // dump partials: slab g, layout [(j*9+d)*128 + c] == transposed flat
        #pragma unroll
        for (int j = 0; j < 4; ++j)
            #pragma unroll
            for (int d = 0; d < 9; ++d)
                buf[g * 4608 + (j * DX + d) * CH + c] = acc[j][d];
        __syncthreads();

        // reduce both slabs and store (all 256 threads, coalesced)
        for (int e = tid; e < 4608; e += 256) {
            float s = buf[e] + buf[4608 + e];
            dst[(size_t)n0 * (DX * CH) + e] = s * SCALE_IN;
        }
    }
}

// ---------------------------------------------------------------------------
// Kernel 2: sparse Gaunt contraction only. 2 nodes/CTA, 128 threads.
// Reads xct/yct [n][d][c], writes zt [n][d][c] (SCALE_OUT folded).
// ---------------------------------------------------------------------------
__global__ void __launch_bounds__(128) k_gaunt(GTab gt)
{
    __shared__ float xcs[2 * DX * CH];
    __shared__ float ycs[2 * DX * CH];

    const int t  = threadIdx.x;
    const int n0 = blockIdx.x * 2;

    for (int i = t; i < 2 * DX * CH; i += 128) {
        xcs[i] = g_xct[(size_t)n0 * DX * CH + i];
        ycs[i] = g_yct[(size_t)n0 * DX * CH + i];
    }
    __syncthreads();

    const float* x0 = xcs + t;
    const float* x1 = xcs + DX * CH + t;
    const float* y0 = ycs + t;
    const float* y1 = ycs + DX * CH + t;
    float* o0 = g_zt + (size_t)n0 * DZ * CH + t;
    float* o1 = o0 + DZ * CH;

    for (int d = 0; d < DZ; ++d) {
        float z0 = 0.0f, z1 = 0.0f;
        const int e0 = gt.start[d], e1 = gt.start[d + 1];
        for (int k = e0; k < e1; ++k) {
            const int   id = gt.idx[k];
            const float cf = gt.coef[k];
            const int a1 = (id >> 8) * CH;
            const int a2 = (id & 255) * CH;
            z0 = fmaf(cf, x0[a1] * y0[a2], z0);
            z1 = fmaf(cf, x1[a1] * y1[a2], z1);
        }
        o0[d * CH] = z0 * SCALE_OUT;
        o1[d * CH] = z1 * SCALE_OUT;
    }
}

// ---------------------------------------------------------------------------
// Kernel 3: linear_out as d-batched double-buffered SGEMM.
//   For fixed d: C[n][e] = sum_c zt[n][d][c] * wz[l(d)][c][e]
// grid (16, 25): CTA = 64 n-rows x 128 e-cols, K = 128 in chunks of 32.
// 256 threads, 4x8 micro-tile. Dynamic smem = 51200 B.
// ---------------------------------------------------------------------------
#define KC  32
#define PAK 36    // A row pitch (32 + 4): conflict-free, float4-aligned

__global__ void __launch_bounds__(256) k_out(
    const float* __restrict__ wz, float* __restrict__ out)
{
    extern __shared__ float sm[];
    float* As = sm;                    // [2][64][PAK]  (row-major, k minor)
    float* Bs = sm + 2 * 64 * PAK;     // [2][KC][128]

    const int d   = blockIdx.y;
    const int l   = (d >= 16) ? 4 : (d >= 9) ? 3 : (d >= 4) ? 2 : (d >= 1) ? 1 : 0;
    const int n0  = blockIdx.x * 64;
    const int tid = threadIdx.x;

    const float* Ab = g_zt + (size_t)n0 * (DZ * CH) + (size_t)d * CH;
    const float* Bb = wz + (size_t)l * (CH * CH);

    // loader lanes
    const int ar  = tid >> 3;     // 0..31 : A row (+32 on 2nd sweep)
    const int as  = tid & 7;      // float4 slot within 32-float k-chunk
    const int be4 = tid & 31;     // B float4 col
    const int bk  = tid >> 5;     // 0..7  : B k row (+8 per sweep)

    float4 pa[2], pb[4];

    // micro-tile lanes
    const int tm = tid >> 4;      // 0..15 -> rows tm*4 .. tm*4+3
    const int te = tid & 15;      // cols te*4..+3 and 64+te*4..+3

    float acc[4][8];
    #pragma unroll
    for (int i = 0; i < 4; ++i)
        #pragma unroll
        for (int j = 0; j < 8; ++j) acc[i][j] = 0.0f;

    // prologue: load chunk 0
    #pragma unroll
    for (int s = 0; s < 2; ++s)
        pa[s] = *(const float4*)(Ab + (size_t)(ar + s * 32) * (DZ * CH) + as * 4);
    #pragma unroll
    for (int s = 0; s < 4; ++s)
        pb[s] = *(const float4*)(Bb + (size_t)(bk + s * 8) * CH + be4 * 4);
    {
        float* A = As; float* B = Bs;
        #pragma unroll
        for (int s = 0; s < 2; ++s)
            *(float4*)(A + (ar + s * 32) * PAK + as * 4) = pa[s];
        #pragma unroll
        for (int s = 0; s < 4; ++s)
            *(float4*)(B + (bk + s * 8) * 128 + be4 * 4) = pb[s];
    }
    __syncthreads();

    for (int kb = 0; kb < 4; ++kb) {
        if (kb < 3) {
            const int ko = (kb + 1) * KC;
            #pragma unroll
            for (int s = 0; s < 2; ++s)
                pa[s] = *(const float4*)(Ab + (size_t)(ar + s * 32) * (DZ * CH) + ko + as * 4);
            #pragma unroll
            for (int s = 0; s < 4; ++s)
                pb[s] = *(const float4*)(Bb + (size_t)(ko + bk + s * 8) * CH + be4 * 4);
        }

        const float* A = As + (kb & 1) * 64 * PAK;
        const float* B = Bs + (kb & 1) * KC * 128;

        #pragma unroll 8
        for (int kk = 0; kk < KC; ++kk) {
            float a0 = A[(tm * 4 + 0) * PAK + kk];
            float a1 = A[(tm * 4 + 1) * PAK + kk];
            float a2 = A[(tm * 4 + 2) * PAK + kk];
            float a3 = A[(tm * 4 + 3) * PAK + kk];
            float4 b0 = *(const float4*)(B + kk * 128 + te * 4);
            float4 b1 = *(const float4*)(B + kk * 128 + 64 + te * 4);
            float bv[8] = {b0.x, b0.y, b0.z, b0.w, b1.x, b1.y, b1.z, b1.w};
            #pragma unroll
            for (int j = 0; j < 8; ++j) {
                acc[0][j] = fmaf(a0, bv[j], acc[0][j]);
                acc[1][j] = fmaf(a1, bv[j], acc[1][j]);
                acc[2][j] = fmaf(a2, bv[j], acc[2][j]);
                acc[3][j] = fmaf(a3, bv[j], acc[3][j]);
            }
        }

        if (kb < 3) {
            __syncthreads();
            float* An = As + ((kb + 1) & 1) * 64 * PAK;
            float* Bn = Bs + ((kb + 1) & 1) * KC * 128;
            #pragma unroll
            for (int s = 0; s < 2; ++s)
                *(float4*)(An + (ar + s * 32) * PAK + as * 4) = pa[s];
            #pragma unroll
            for (int s = 0; s < 4; ++s)
                *(float4*)(Bn + (bk + s * 8) * 128 + be4 * 4) = pb[s];
            __syncthreads();
        }
    }

    // store: out[n][e][d]
    #pragma unroll
    for (int i = 0; i < 4; ++i) {
        const int n = n0 + tm * 4 + i;
        float* op = out + (size_t)n * (CH * DZ) + d;
        #pragma unroll
        for (int j = 0; j < 8; ++j) {
            const int e = (j < 4) ? (te * 4 + j) : (64 + te * 4 + (j - 4));
            op[(size_t)e * DZ] = acc[i][j];
        }
    }
}

// ---------------------------------------------------------------------------
extern "C" void kernel_launch(void* const* d_in, const int* in_sizes, int n_in,
                              void* d_out, int out_size)
{
    const float* x  = (const float*)d_in[0];
    const float* y  = (const float*)d_in[1];
    const float* wx = (const float*)d_in[2];
    const float* wy = (const float*)d_in[3];
    const float* wz = (const float*)d_in[4];
    float* out = (float*)d_out;

    GTab gt;
    build_gtab(&gt);

    const int smem_lin = (4 * MUL * 12 + 2 * 4608) * 4;        // 61440 B
    const int smem_out = (2 * 64 * PAK + 2 * KC * 128) * 4;    // 51200 B
    cudaFuncSetAttribute(k_lin_in, cudaFuncAttributeMaxDynamicSharedMemorySize, smem_lin);
    cudaFuncSetAttribute(k_out,    cudaFuncAttributeMaxDynamicSharedMemorySize, smem_out);

    k_lin_in<<<NN / 4, 256, smem_lin>>>(x, y, wx, wy);
    k_gaunt<<<NN / 2, 128>>>(gt);

    dim3 g3(16, 25);
    k_out<<<g3, 256, smem_out>>>(wz, out);
}

// round 9
// speedup vs baseline: 1.6352x; 1.2297x over previous
#include <cuda_runtime.h>
#include <math.h>
#include <string.h>

// Problem constants
#define NN   1024
#define MUL  128
#define CH   128
#define RBq  20
#define RAq  19
#define DX   9     // (L1+1)^2 = (L2+1)^2
#define DZ   25    // (LZ+1)^2
#define MAXG 480

#define SCALE_IN  0.08838834764831845f   // 1/sqrt(128)
#define SCALE_OUT 0.08838834764831845f   // 1/sqrt(128)

// Sparse Gaunt table, passed by value as kernel parameter (constant memory).
struct GTab {
    int   start[DZ + 1];
    int   idx[MAXG];       // (d1 << 8) | d2
    float coef[MAXG];
};

// Intermediates
__device__ float g_xt [NN * DX * MUL];   // x transposed [n][d][m]
__device__ float g_yt [NN * DX * MUL];   // y transposed [n][d][m]
__device__ float g_xct[NN * DX * CH];    // [n][d][c]
__device__ float g_yct[NN * DX * CH];
__device__ float g_zt [NN * DZ * CH];    // [n][d][c]

// ---------------------------------------------------------------------------
// Host: build the Gaunt table (double precision, exact quadrature as ref)
// ---------------------------------------------------------------------------
static double assoc_legendre_h(int l, int m, double x) {
    double pmm = 1.0;
    if (m > 0) {
        double df = 1.0;
        for (int i = 1; i < 2 * m; i += 2) df *= (double)i;
        pmm = ((m & 1) ? -1.0 : 1.0) * df * pow(1.0 - x * x, 0.5 * m);
    }
    if (l == m) return pmm;
    double pmmp1 = x * (2 * m + 1) * pmm;
    if (l == m + 1) return pmmp1;
    double p = pmmp1;
    for (int ll = m + 2; ll <= l; ++ll) {
        p = ((2 * ll - 1) * x * pmmp1 - (ll + m - 1) * pmm) / (ll - m);
        pmm = pmmp1; pmmp1 = p;
    }
    return pmmp1;
}

static void build_gtab(GTab* gt) {
    double ct[RBq], qw[RBq];
    const int n = RBq;
    for (int i = 0; i < n; ++i) {
        double z = cos(M_PI * (i + 0.75) / (n + 0.5));
        double pp = 1.0;
        for (int it = 0; it < 100; ++it) {
            double p1 = 1.0, p2 = 0.0;
            for (int j = 1; j <= n; ++j) {
                double p3 = p2; p2 = p1;
                p1 = ((2.0 * j - 1.0) * z * p2 - (j - 1.0) * p3) / (double)j;
            }
            pp = n * (z * p1 - p2) / (z * z - 1.0);
            double dz = p1 / pp;
            z -= dz;
            if (fabs(dz) < 1e-15) break;
        }
        ct[i] = z;
        qw[i] = 2.0 / ((1.0 - z * z) * pp * pp);
    }

    static double Y[DZ][RBq][RAq];
    for (int l = 0; l <= 4; ++l) {
        for (int m = -l; m <= l; ++m) {
            int am = m < 0 ? -m : m;
            double f1 = 1.0, f2 = 1.0;
            for (int i = 2; i <= l - am; ++i) f1 *= (double)i;
            for (int i = 2; i <= l + am; ++i) f2 *= (double)i;
            double nlm = sqrt((2.0 * l + 1.0) / (4.0 * M_PI) * f1 / f2);
            for (int b = 0; b < RBq; ++b) {
                double P = assoc_legendre_h(l, am, ct[b]);
                for (int a = 0; a < RAq; ++a) {
                    double alpha = 2.0 * M_PI * (double)a / (double)RAq;
                    double ang;
                    if (m == 0)      ang = 1.0;
                    else if (m > 0)  ang = sqrt(2.0) * cos(m * alpha);
                    else             ang = sqrt(2.0) * sin(am * alpha);
                    Y[l * l + l + m][b][a] = nlm * P * ang;
                }
            }
        }
    }

    int cnt = 0;
    for (int d = 0; d < DZ; ++d) {
        gt->start[d] = cnt;
        for (int d1 = 0; d1 < DX; ++d1) {
            for (int d2 = 0; d2 < DX; ++d2) {
                double s = 0.0;
                for (int b = 0; b < RBq; ++b) {
                    double rs = 0.0;
                    for (int a = 0; a < RAq; ++a)
                        rs += Y[d][b][a] * Y[d1][b][a] * Y[d2][b][a];
                    s += rs * qw[b];
                }
                s *= 2.0 * M_PI / (double)RAq;
                if (fabs(s) > 1e-8 && cnt < MAXG) {
                    gt->idx[cnt]  = (d1 << 8) | d2;
                    gt->coef[cnt] = (float)s;
                    ++cnt;
                }
            }
        }
    }
    gt->start[DZ] = cnt;
    for (int k = cnt; k < MAXG; ++k) { gt->idx[k] = 0; gt->coef[k] = 0.0f; }
}

// ---------------------------------------------------------------------------
// Kernel 0: transpose x,y [n][m][9] -> [n][9][m]. 4 nodes/CTA, 256 threads.
// ---------------------------------------------------------------------------
__global__ void __launch_bounds__(256) k_tr(
    const float* __restrict__ x, const float* __restrict__ y)
{
    __shared__ float sm[4 * MUL * DX];   // 18432 B
    const int tid = threadIdx.x;
    const int n0  = blockIdx.x * 4;
    const int NB  = 4 * MUL * DX;        // 4608

    for (int pass = 0; pass < 2; ++pass) {
        const float* src = pass ? y    : x;
        float*       dst = pass ? g_yt : g_xt;

        __syncthreads();
        for (int i = tid; i < NB; i += 256)
            sm[i] = src[(size_t)n0 * (MUL * DX) + i];
        __syncthreads();
        for (int o = tid; o < NB; o += 256) {
            int j = o / (DX * MUL);
            int r = o - j * (DX * MUL);
            int d = r >> 7;              // r / 128
            int m = r & 127;
            dst[(size_t)n0 * (DX * MUL) + o] = sm[j * (MUL * DX) + m * DX + d];
        }
    }
}

// ---------------------------------------------------------------------------
// Kernel 1: linear_in as d-batched double-buffered SGEMM.
//   For batch b: d = b%9, tensor = b/9.  C[n][c] = sum_m A[n][d][m] * w[l][m][c]
// grid (16, 18): CTA = 64 n-rows x 128 c-cols, K = 128 in chunks of 32.
// 256 threads, 4x8 micro-tile. Dynamic smem = 51200 B.
// ---------------------------------------------------------------------------
#define KC  32
#define PAK 36    // A row pitch (32 + 4): conflict-free, float4-aligned

__global__ void __launch_bounds__(256) k_lin_gemm(
    const float* __restrict__ wx, const float* __restrict__ wy)
{
    extern __shared__ float sm[];
    float* As = sm;                    // [2][64][PAK]
    float* Bs = sm + 2 * 64 * PAK;     // [2][KC][128]

    const int b    = blockIdx.y;
    const int is_y = (b >= DX);
    const int d    = is_y ? (b - DX) : b;
    const int l    = (d >= 4) ? 2 : (d >= 1) ? 1 : 0;
    const int n0   = blockIdx.x * 64;
    const int tid  = threadIdx.x;

    const float* Ab = (is_y ? g_yt : g_xt) + (size_t)n0 * (DX * MUL) + (size_t)d * MUL;
    const float* Bb = (is_y ? wy : wx) + (size_t)l * (MUL * CH);
    float*       Cb = (is_y ? g_yct : g_xct) + (size_t)n0 * (DX * CH) + (size_t)d * CH;

    const int ar  = tid >> 3;     // 0..31 : A row (+32 on 2nd sweep)
    const int as  = tid & 7;
    const int be4 = tid & 31;
    const int bk  = tid >> 5;

    float4 pa[2], pb[4];

    const int tm = tid >> 4;
    const int te = tid & 15;

    float acc[4][8];
    #pragma unroll
    for (int i = 0; i < 4; ++i)
        #pragma unroll
        for (int j = 0; j < 8; ++j) acc[i][j] = 0.0f;

    #pragma unroll
    for (int s = 0; s < 2; ++s)
        pa[s] = *(const float4*)(Ab + (size_t)(ar + s * 32) * (DX * MUL) + as * 4);
    #pragma unroll
    for (int s = 0; s < 4; ++s)
        pb[s] = *(const float4*)(Bb + (size_t)(bk + s * 8) * CH + be4 * 4);
    #pragma unroll
    for (int s = 0; s < 2; ++s)
        *(float4*)(As + (ar + s * 32) * PAK + as * 4) = pa[s];
    #pragma unroll
    for (int s = 0; s < 4; ++s)
        *(float4*)(Bs + (bk + s * 8) * 128 + be4 * 4) = pb[s];
    __syncthreads();

    for (int kb = 0; kb < 4; ++kb) {
        if (kb < 3) {
            const int ko = (kb + 1) * KC;
            #pragma unroll
            for (int s = 0; s < 2; ++s)
                pa[s] = *(const float4*)(Ab + (size_t)(ar + s * 32) * (DX * MUL) + ko + as * 4);
            #pragma unroll
            for (int s = 0; s < 4; ++s)
                pb[s] = *(const float4*)(Bb + (size_t)(ko + bk + s * 8) * CH + be4 * 4);
        }

        const float* A = As + (kb & 1) * 64 * PAK;
        const float* B = Bs + (kb & 1) * KC * 128;

        #pragma unroll 8
        for (int kk = 0; kk < KC; ++kk) {
            float a0 = A[(tm * 4 + 0) * PAK + kk];
            float a1 = A[(tm * 4 + 1) * PAK + kk];
            float a2 = A[(tm * 4 + 2) * PAK + kk];
            float a3 = A[(tm * 4 + 3) * PAK + kk];
            float4 b0 = *(const float4*)(B + kk * 128 + te * 4);
            float4 b1 = *(const float4*)(B + kk * 128 + 64 + te * 4);
            float bv[8] = {b0.x, b0.y, b0.z, b0.w, b1.x, b1.y, b1.z, b1.w};
            #pragma unroll
            for (int j = 0; j < 8; ++j) {
                acc[0][j] = fmaf(a0, bv[j], acc[0][j]);
                acc[1][j] = fmaf(a1, bv[j], acc[1][j]);
                acc[2][j] = fmaf(a2, bv[j], acc[2][j]);
                acc[3][j] = fmaf(a3, bv[j], acc[3][j]);
            }
        }

        if (kb < 3) {
            __syncthreads();
            float* An = As + ((kb + 1) & 1) * 64 * PAK;
            float* Bn = Bs + ((kb + 1) & 1) * KC * 128;
            #pragma unroll
            for (int s = 0; s < 2; ++s)
                *(float4*)(An + (ar + s * 32) * PAK + as * 4) = pa[s];
            #pragma unroll
            for (int s = 0; s < 4; ++s)
                *(float4*)(Bn + (bk + s * 8) * 128 + be4 * 4) = pb[s];
            __syncthreads();
        }
    }

    // store contiguous float4 into [n][d][c]
    #pragma unroll
    for (int i = 0; i < 4; ++i) {
        float* cp = Cb + (size_t)(tm * 4 + i) * (DX * CH);
        float4 v0 = make_float4(acc[i][0] * SCALE_IN, acc[i][1] * SCALE_IN,
                                acc[i][2] * SCALE_IN, acc[i][3] * SCALE_IN);
        float4 v1 = make_float4(acc[i][4] * SCALE_IN, acc[i][5] * SCALE_IN,
                                acc[i][6] * SCALE_IN, acc[i][7] * SCALE_IN);
        *(float4*)(cp + te * 4)      = v0;
        *(float4*)(cp + 64 + te * 4) = v1;
    }
}

// ---------------------------------------------------------------------------
// Kernel 2: sparse Gaunt contraction. 2 nodes/CTA, 128 threads.
// ---------------------------------------------------------------------------
__global__ void __launch_bounds__(128) k_gaunt(GTab gt)
{
    __shared__ float xcs[2 * DX * CH];
    __shared__ float ycs[2 * DX * CH];

    const int t  = threadIdx.x;
    const int n0 = blockIdx.x * 2;

    for (int i = t; i < 2 * DX * CH; i += 128) {
        xcs[i] = g_xct[(size_t)n0 * DX * CH + i];
        ycs[i] = g_yct[(size_t)n0 * DX * CH + i];
    }
    __syncthreads();

    const float* x0 = xcs + t;
    const float* x1 = xcs + DX * CH + t;
    const float* y0 = ycs + t;
    const float* y1 = ycs + DX * CH + t;
    float* o0 = g_zt + (size_t)n0 * DZ * CH + t;
    float* o1 = o0 + DZ * CH;

    for (int d = 0; d < DZ; ++d) {
        float z0 = 0.0f, z1 = 0.0f;
        const int e0 = gt.start[d], e1 = gt.start[d + 1];
        for (int k = e0; k < e1; ++k) {
            const int   id = gt.idx[k];
            const float cf = gt.coef[k];
            const int a1 = (id >> 8) * CH;
            const int a2 = (id & 255) * CH;
            z0 = fmaf(cf, x0[a1] * y0[a2], z0);
            z1 = fmaf(cf, x1[a1] * y1[a2], z1);
        }
        o0[d * CH] = z0 * SCALE_OUT;
        o1[d * CH] = z1 * SCALE_OUT;
    }
}

// ---------------------------------------------------------------------------
// Kernel 3: linear_out as d-batched double-buffered SGEMM (proven config).
// ---------------------------------------------------------------------------
__global__ void __launch_bounds__(256) k_out(
    const float* __restrict__ wz, float* __restrict__ out)
{
    extern __shared__ float sm[];
    float* As = sm;                    // [2][64][PAK]
    float* Bs = sm + 2 * 64 * PAK;     // [2][KC][128]

    const int d   = blockIdx.y;
    const int l   = (d >= 16) ? 4 : (d >= 9) ? 3 : (d >= 4) ? 2 : (d >= 1) ? 1 : 0;
    const int n0  = blockIdx.x * 64;
    const int tid = threadIdx.x;

    const float* Ab = g_zt + (size_t)n0 * (DZ * CH) + (size_t)d * CH;
    const float* Bb = wz + (size_t)l * (CH * CH);

    const int ar  = tid >> 3;
    const int as  = tid & 7;
    const int be4 = tid & 31;
    const int bk  = tid >> 5;

    float4 pa[2], pb[4];

    const int tm = tid >> 4;
    const int te = tid & 15;

    float acc[4][8];
    #pragma unroll
    for (int i = 0; i < 4; ++i)
        #pragma unroll
        for (int j = 0; j < 8; ++j) acc[i][j] = 0.0f;

    #pragma unroll
    for (int s = 0; s < 2; ++s)
        pa[s] = *(const float4*)(Ab + (size_t)(ar + s * 32) * (DZ * CH) + as * 4);
    #pragma unroll
    for (int s = 0; s < 4; ++s)
        pb[s] = *(const float4*)(Bb + (size_t)(bk + s * 8) * CH + be4 * 4);
    #pragma unroll
    for (int s = 0; s < 2; ++s)
        *(float4*)(As + (ar + s * 32) * PAK + as * 4) = pa[s];
    #pragma unroll
    for (int s = 0; s < 4; ++s)
        *(float4*)(Bs + (bk + s * 8) * 128 + be4 * 4) = pb[s];
    __syncthreads();

    for (int kb = 0; kb < 4; ++kb) {
        if (kb < 3) {
            const int ko = (kb + 1) * KC;
            #pragma unroll
            for (int s = 0; s < 2; ++s)
                pa[s] = *(const float4*)(Ab + (size_t)(ar + s * 32) * (DZ * CH) + ko + as * 4);
            #pragma unroll
            for (int s = 0; s < 4; ++s)
                pb[s] = *(const float4*)(Bb + (size_t)(ko + bk + s * 8) * CH + be4 * 4);
        }

        const float* A = As + (kb & 1) * 64 * PAK;
        const float* B = Bs + (kb & 1) * KC * 128;

        #pragma unroll 8
        for (int kk = 0; kk < KC; ++kk) {
            float a0 = A[(tm * 4 + 0) * PAK + kk];
            float a1 = A[(tm * 4 + 1) * PAK + kk];
            float a2 = A[(tm * 4 + 2) * PAK + kk];
            float a3 = A[(tm * 4 + 3) * PAK + kk];
            float4 b0 = *(const float4*)(B + kk * 128 + te * 4);
            float4 b1 = *(const float4*)(B + kk * 128 + 64 + te * 4);
            float bv[8] = {b0.x, b0.y, b0.z, b0.w, b1.x, b1.y, b1.z, b1.w};
            #pragma unroll
            for (int j = 0; j < 8; ++j) {
                acc[0][j] = fmaf(a0, bv[j], acc[0][j]);
                acc[1][j] = fmaf(a1, bv[j], acc[1][j]);
                acc[2][j] = fmaf(a2, bv[j], acc[2][j]);
                acc[3][j] = fmaf(a3, bv[j], acc[3][j]);
            }
        }

        if (kb < 3) {
            __syncthreads();
            float* An = As + ((kb + 1) & 1) * 64 * PAK;
            float* Bn = Bs + ((kb + 1) & 1) * KC * 128;
            #pragma unroll
            for (int s = 0; s < 2; ++s)
                *(float4*)(An + (ar + s * 32) * PAK + as * 4) = pa[s];
            #pragma unroll
            for (int s = 0; s < 4; ++s)
                *(float4*)(Bn + (bk + s * 8) * 128 + be4 * 4) = pb[s];
            __syncthreads();
        }
    }

    // store: out[n][e][d]
    #pragma unroll
    for (int i = 0; i < 4; ++i) {
        const int n = n0 + tm * 4 + i;
        float* op = out + (size_t)n * (CH * DZ) + d;
        #pragma unroll
        for (int j = 0; j < 8; ++j) {
            const int e = (j < 4) ? (te * 4 + j) : (64 + te * 4 + (j - 4));
            op[(size_t)e * DZ] = acc[i][j];
        }
    }
}

// ---------------------------------------------------------------------------
extern "C" void kernel_launch(void* const* d_in, const int* in_sizes, int n_in,
                              void* d_out, int out_size)
{
    const float* x  = (const float*)d_in[0];
    const float* y  = (const float*)d_in[1];
    const float* wx = (const float*)d_in[2];
    const float* wy = (const float*)d_in[3];
    const float* wz = (const float*)d_in[4];
    float* out = (float*)d_out;

    GTab gt;
    build_gtab(&gt);

    const int smem_gemm = (2 * 64 * PAK + 2 * KC * 128) * 4;   // 51200 B
    cudaFuncSetAttribute(k_lin_gemm, cudaFuncAttributeMaxDynamicSharedMemorySize, smem_gemm);
    cudaFuncSetAttribute(k_out,      cudaFuncAttributeMaxDynamicSharedMemorySize, smem_gemm);

    k_tr<<<NN / 4, 256>>>(x, y);

    dim3 g1(16, 2 * DX);
    k_lin_gemm<<<g1, 256, smem_gemm>>>(wx, wy);

    k_gaunt<<<NN / 2, 128>>>(gt);

    dim3 g3(16, DZ);
    k_out<<<g3, 256, smem_gemm>>>(wz, out);
}